// round 3
// baseline (speedup 1.0000x reference)
#include <cuda_runtime.h>

// SiluAndMul: x [M, 2N] fp32 -> out [M, N] fp32, out = silu(x[:, :N]) * x[:, N:]
// M = 16384, N = 11008. Pure HBM-bound: 2.164 GB traffic, floor ~300us @ 7.2TB/s achieved.
// R3: 4x float4 per thread (8 front-batched LDG.128 -> 4 STG.128) to lengthen
// read/write bursts at the memory controller and deepen MLP.

static constexpr int M = 16384;
static constexpr int N = 11008;         // output cols
static constexpr int TWO_N = 2 * N;     // input row stride (floats)
static constexpr int N4 = N / 4;        // 2752 float4 per output row
static constexpr int BLOCK = 256;
static constexpr int VEC = 4;           // float4 per thread
static constexpr int COLS_PER_BLOCK = VEC * BLOCK;            // 1024 float4 cols
static constexpr int GRID_X = (N4 + COLS_PER_BLOCK - 1) / COLS_PER_BLOCK;  // 3

__device__ __forceinline__ float silu(float g) {
    return g * __frcp_rn(1.0f + __expf(-g));
}

__global__ __launch_bounds__(BLOCK) void silu_and_mul_kernel(
    const float* __restrict__ x, float* __restrict__ out)
{
    const long long row = blockIdx.y;
    const int base = blockIdx.x * COLS_PER_BLOCK + threadIdx.x;

    const float4* gate4 = reinterpret_cast<const float4*>(x + row * TWO_N);
    const float4* up4   = reinterpret_cast<const float4*>(x + row * TWO_N + N);
    float4* out4        = reinterpret_cast<float4*>(out + row * (long long)N);

    int   c[VEC];
    bool  p[VEC];
    float4 g[VEC], u[VEC];

    #pragma unroll
    for (int i = 0; i < VEC; i++) {
        c[i] = base + i * BLOCK;
        p[i] = (c[i] < N4);
    }

    // Front-batch all 8 loads (gate then up) for maximum MLP and long read bursts.
    #pragma unroll
    for (int i = 0; i < VEC; i++) if (p[i]) g[i] = __ldcs(&gate4[c[i]]);
    #pragma unroll
    for (int i = 0; i < VEC; i++) if (p[i]) u[i] = __ldcs(&up4[c[i]]);

    // Compute, then one store burst.
    #pragma unroll
    for (int i = 0; i < VEC; i++) {
        if (p[i]) {
            float4 r;
            r.x = silu(g[i].x) * u[i].x;
            r.y = silu(g[i].y) * u[i].y;
            r.z = silu(g[i].z) * u[i].z;
            r.w = silu(g[i].w) * u[i].w;
            __stcs(&out4[c[i]], r);
        }
    }
}

extern "C" void kernel_launch(void* const* d_in, const int* in_sizes, int n_in,
                              void* d_out, int out_size)
{
    const float* x = (const float*)d_in[0];
    float* out = (float*)d_out;

    dim3 block(BLOCK);
    dim3 grid(GRID_X, M);   // (3, 16384)
    silu_and_mul_kernel<<<grid, block>>>(x, out);
}

// round 4
// speedup vs baseline: 1.0085x; 1.0085x over previous
#include <cuda_runtime.h>

// SiluAndMul: x [M, 2N] fp32 -> out [M, N] fp32, out = silu(x[:, :N]) * x[:, N:]
// M = 16384, N = 11008. HBM-bound: 2.164 GB/launch, ~7.15 TB/s practical ceiling.
// R4: R1 shape (1 float4/thread, occ 80%) + evict-normal input loads (preserve
// cross-replay L2 residency of input) + evict-first output stores (don't let
// never-re-read output displace input lines in the 126MB L2).

static constexpr int M = 16384;
static constexpr int N = 11008;         // output cols
static constexpr int TWO_N = 2 * N;     // input row stride (floats)
static constexpr int N4 = N / 4;        // 2752 float4 per output row

__global__ __launch_bounds__(256) void silu_and_mul_kernel(
    const float* __restrict__ x, float* __restrict__ out)
{
    const int col4 = blockIdx.x * blockDim.x + threadIdx.x;  // float4 column index
    if (col4 >= N4) return;
    const long long row = blockIdx.y;

    const float4* gate4 = reinterpret_cast<const float4*>(x + row * TWO_N);
    const float4* up4   = reinterpret_cast<const float4*>(x + row * TWO_N + N);
    float4* out4        = reinterpret_cast<float4*>(out + row * (long long)N);

    // Evict-normal loads: input lines may survive in L2 across graph replays.
    float4 g = gate4[col4];
    float4 u = up4[col4];

    float4 r;
    r.x = (g.x * __frcp_rn(1.0f + __expf(-g.x))) * u.x;
    r.y = (g.y * __frcp_rn(1.0f + __expf(-g.y))) * u.y;
    r.z = (g.z * __frcp_rn(1.0f + __expf(-g.z))) * u.z;
    r.w = (g.w * __frcp_rn(1.0f + __expf(-g.w))) * u.w;

    // Evict-first store: output is never re-read, keep it out of L2.
    __stcs(&out4[col4], r);
}

extern "C" void kernel_launch(void* const* d_in, const int* in_sizes, int n_in,
                              void* d_out, int out_size)
{
    const float* x = (const float*)d_in[0];
    float* out = (float*)d_out;

    dim3 block(256);
    dim3 grid((N4 + 255) / 256, M);   // (11, 16384)
    silu_and_mul_kernel<<<grid, block>>>(x, out);
}

// round 5
// speedup vs baseline: 1.0140x; 1.0054x over previous
#include <cuda_runtime.h>

// SiluAndMul: x [M, 2N] fp32 -> out [M, N] fp32, out = silu(x[:, :N]) * x[:, N:]
// M = 16384, N = 11008. Pure HBM-bound: 2.164 GB/launch.
// Converged config (best of 5 variants): plain evict-normal loads AND stores
// (both streaming hints measured ~2us slower each — evict-first writebacks
// interleave with reads and add DRAM bus turnarounds), 1 float4/thread,
// 256-thread blocks, 2D grid. Runs at ~7.2 TB/s = the measured HBM ceiling;
// dur ~299.5us vs 299.7us analytic floor at that bandwidth.

static constexpr int M = 16384;
static constexpr int N = 11008;         // output cols
static constexpr int TWO_N = 2 * N;     // input row stride (floats)
static constexpr int N4 = N / 4;        // 2752 float4 per output row

__global__ __launch_bounds__(256) void silu_and_mul_kernel(
    const float* __restrict__ x, float* __restrict__ out)
{
    const int col4 = blockIdx.x * blockDim.x + threadIdx.x;  // float4 column index
    if (col4 >= N4) return;
    const long long row = blockIdx.y;

    const float4* gate4 = reinterpret_cast<const float4*>(x + row * TWO_N);
    const float4* up4   = reinterpret_cast<const float4*>(x + row * TWO_N + N);
    float4* out4        = reinterpret_cast<float4*>(out + row * (long long)N);

    float4 g = gate4[col4];
    float4 u = up4[col4];

    float4 r;
    r.x = (g.x * __frcp_rn(1.0f + __expf(-g.x))) * u.x;
    r.y = (g.y * __frcp_rn(1.0f + __expf(-g.y))) * u.y;
    r.z = (g.z * __frcp_rn(1.0f + __expf(-g.z))) * u.z;
    r.w = (g.w * __frcp_rn(1.0f + __expf(-g.w))) * u.w;

    out4[col4] = r;
}

extern "C" void kernel_launch(void* const* d_in, const int* in_sizes, int n_in,
                              void* d_out, int out_size)
{
    const float* x = (const float*)d_in[0];
    float* out = (float*)d_out;

    dim3 block(256);
    dim3 grid((N4 + 255) / 256, M);   // (11, 16384)
    silu_and_mul_kernel<<<grid, block>>>(x, out);
}